// round 4
// baseline (speedup 1.0000x reference)
#include <cuda_runtime.h>
#include <cstdint>
#include <cstddef>

// ---------------- problem constants ----------------
#define FANOUT 10
#define N0_SZ 1362944
#define N1_SZ 123904
#define N2_SZ 11264
#define SEEDS_SZ 1024
#define IN_DIM 256
#define H_DIM 512
#define C_DIM 256

// ---------------- device scratch (allocation-free rule) ----------------
// All "A-side" scratch is stored tf32-rounded AND k-permuted (within each
// 8-group: pos(i) = (i&3)*2 + (i>>2)) so GEMM fragment loads are float2.
__device__ __align__(16) float g_xr[(size_t)N1_SZ * IN_DIM];       // rounded+perm x[:N1]
__device__ __align__(16) float g_neigh0[(size_t)N1_SZ * IN_DIM];
__device__ __align__(16) float g_h1[(size_t)N1_SZ * H_DIM];
__device__ __align__(16) float g_neigh1[(size_t)N2_SZ * H_DIM];
__device__ __align__(16) float g_h2[(size_t)N2_SZ * H_DIM];
__device__ __align__(16) float g_neigh2[(size_t)SEEDS_SZ * H_DIM];
// transposed + tf32-rounded + k-permuted weights: Wt[n][perm(k)] = tf32(W[k][n])
__device__ __align__(16) float g_Wt0s[(size_t)H_DIM * IN_DIM];
__device__ __align__(16) float g_Wt0n[(size_t)H_DIM * IN_DIM];
__device__ __align__(16) float g_Wt1s[(size_t)H_DIM * H_DIM];
__device__ __align__(16) float g_Wt1n[(size_t)H_DIM * H_DIM];
__device__ __align__(16) float g_Wt2s[(size_t)C_DIM * H_DIM];
__device__ __align__(16) float g_Wt2n[(size_t)C_DIM * H_DIM];

// ---------------- helpers (portable sm_80+ PTX) ----------------
__device__ __forceinline__ uint32_t smem_u32(const void* p) {
    uint32_t a;
    asm("{ .reg .u64 t; cvta.to.shared.u64 t, %1; cvt.u32.u64 %0, t; }" : "=r"(a) : "l"(p));
    return a;
}
__device__ __forceinline__ float cvt_tf32(float x) {
    float r; asm("cvt.rna.tf32.f32 %0, %1;" : "=f"(r) : "f"(x)); return r;
}
__device__ __forceinline__ void cp_async16(uint32_t dst, const void* src) {
    asm volatile("cp.async.cg.shared.global [%0], [%1], 16;" :: "r"(dst), "l"(src));
}
#define CP_COMMIT() asm volatile("cp.async.commit_group;" ::: "memory")
#define CP_WAIT(n)  asm volatile("cp.async.wait_group %0;" :: "n"(n) : "memory")

__device__ __forceinline__ void mma_tf32(float c[4],
                                         uint32_t a0, uint32_t a1, uint32_t a2, uint32_t a3,
                                         uint32_t b0, uint32_t b1) {
    asm volatile(
        "mma.sync.aligned.m16n8k8.row.col.f32.tf32.tf32.f32 "
        "{%0,%1,%2,%3}, {%4,%5,%6,%7}, {%8,%9}, {%0,%1,%2,%3};"
        : "+f"(c[0]), "+f"(c[1]), "+f"(c[2]), "+f"(c[3])
        : "r"(a0), "r"(a1), "r"(a2), "r"(a3), "r"(b0), "r"(b1));
}

__host__ __device__ __forceinline__ int perm8(int i) { return (i & 3) * 2 + (i >> 2); }

// ---------------------------------------------------------------------------
// gather-mean: out[d,:] = round(mean_{e<10} h[src[d*10+e], :])
// PERM=true: input unpermuted, output permuted (layer 0, reading raw x).
// PERM=false: input already permuted -> elementwise mean preserves layout.
// blockDim = (dim/8, rowsPerBlk)
// ---------------------------------------------------------------------------
template <bool PERM>
__global__ void gather_mean_kernel(const float* __restrict__ h,
                                   const int* __restrict__ src,
                                   float* __restrict__ out, int dim8, int num_dst) {
    const int d = blockIdx.x * blockDim.y + threadIdx.y;
    if (d >= num_dst) return;
    const int t = threadIdx.x;
    const int* s = src + (size_t)d * FANOUT;
    const float4* h4 = (const float4*)h;

    float4 a0 = make_float4(0.f, 0.f, 0.f, 0.f);
    float4 a1 = make_float4(0.f, 0.f, 0.f, 0.f);
#pragma unroll
    for (int e = 0; e < FANOUT; ++e) {
        int r = __ldg(s + e);
        const float4* p = h4 + ((size_t)r * dim8 + t) * 2;
        float4 v0 = __ldg(p), v1 = __ldg(p + 1);
        a0.x += v0.x; a0.y += v0.y; a0.z += v0.z; a0.w += v0.w;
        a1.x += v1.x; a1.y += v1.y; a1.z += v1.z; a1.w += v1.w;
    }
    const float inv = 1.0f / FANOUT;
    a0.x = cvt_tf32(a0.x * inv); a0.y = cvt_tf32(a0.y * inv);
    a0.z = cvt_tf32(a0.z * inv); a0.w = cvt_tf32(a0.w * inv);
    a1.x = cvt_tf32(a1.x * inv); a1.y = cvt_tf32(a1.y * inv);
    a1.z = cvt_tf32(a1.z * inv); a1.w = cvt_tf32(a1.w * inv);

    float4* o = (float4*)out + ((size_t)d * dim8 + t) * 2;
    if (PERM) {
        // group [k0..k7] -> [k0,k4,k1,k5 | k2,k6,k3,k7]
        o[0] = make_float4(a0.x, a1.x, a0.y, a1.y);
        o[1] = make_float4(a0.z, a1.z, a0.w, a1.w);
    } else {
        o[0] = a0;
        o[1] = a1;
    }
}

// ---------------------------------------------------------------------------
// round+permute copy: dst[r][perm(c)] = tf32(src[r][c]), rows*cols/8 threads
// ---------------------------------------------------------------------------
__global__ void round_perm_kernel(const float* __restrict__ src,
                                  float* __restrict__ dst, size_t n8) {
    size_t id = (size_t)blockIdx.x * blockDim.x + threadIdx.x;
    if (id >= n8) return;
    const float4* p = (const float4*)src + id * 2;
    float4 v0 = __ldg(p), v1 = __ldg(p + 1);
    v0.x = cvt_tf32(v0.x); v0.y = cvt_tf32(v0.y); v0.z = cvt_tf32(v0.z); v0.w = cvt_tf32(v0.w);
    v1.x = cvt_tf32(v1.x); v1.y = cvt_tf32(v1.y); v1.z = cvt_tf32(v1.z); v1.w = cvt_tf32(v1.w);
    float4* o = (float4*)dst + id * 2;
    o[0] = make_float4(v0.x, v1.x, v0.y, v1.y);
    o[1] = make_float4(v0.z, v1.z, v0.w, v1.w);
}

// ---------------------------------------------------------------------------
// W[K,N] -> Wt[N, perm(K)] with tf32 rounding. grid(N/32, K/32), block(32,8)
// ---------------------------------------------------------------------------
__global__ void transpose_tf32_kernel(const float* __restrict__ W,
                                      float* __restrict__ Wt, int K, int N) {
    __shared__ float t[32][33];
    int bx = blockIdx.x * 32, by = blockIdx.y * 32;
#pragma unroll
    for (int i = threadIdx.y; i < 32; i += 8)
        t[i][threadIdx.x] = __ldg(W + (size_t)(by + i) * N + bx + threadIdx.x);
    __syncthreads();
#pragma unroll
    for (int i = threadIdx.y; i < 32; i += 8) {
        int k = by + threadIdx.x;
        int kp = (k & ~7) | perm8(k & 7);
        Wt[(size_t)(bx + i) * K + kp] = cvt_tf32(t[threadIdx.x][i]);
    }
}

// ---------------------------------------------------------------------------
// tf32 mma.sync dual-GEMM: C[M,N] = act(A0 @ W0 + A1 @ W1 + b)
// A0,A1: [M,K] tf32-rounded, k-permuted. B0t,B1t: [N,K] likewise.
// CTA 128x128, BK=32, 8 warps (2m x 4n), warp tile 64x32.
// INTERMEDIATE=true: ReLU + tf32-round + permuted column store (feeds next layer).
// INTERMEDIATE=false: plain bias add, canonical layout (final output).
// ---------------------------------------------------------------------------
#define PADK 40
#define TILE_F (128 * PADK)
#define SMEM_GEMM_BYTES (4 * TILE_F * 4)   // 2 ops x 2 bufs x 20KB

template <bool INTERMEDIATE>
__global__ __launch_bounds__(256, 2)
void sage_mma_gemm(const float* __restrict__ A0, const float* __restrict__ A1,
                   const float* __restrict__ B0t, const float* __restrict__ B1t,
                   const float* __restrict__ bias, float* __restrict__ C,
                   int K, int N) {
    extern __shared__ float sm[];
    const uint32_t sbase = smem_u32(sm);
    const int tid = threadIdx.x, lane = tid & 31, w = tid >> 5;
    const int wm = w >> 2, wn = w & 3;
    const int m0 = blockIdx.y * 128, n0 = blockIdx.x * 128;
    const int kc = K / 32;
    const int T = 2 * kc;

    float acc[4][4][4];
#pragma unroll
    for (int mi = 0; mi < 4; ++mi)
#pragma unroll
        for (int ni = 0; ni < 4; ++ni)
#pragma unroll
            for (int r = 0; r < 4; ++r) acc[mi][ni][r] = 0.f;

    const int srow = tid >> 3;
    const int sc4  = tid & 7;

    auto stage = [&](int chunk, int buf) {
        const int pair = (chunk >= kc) ? 1 : 0;
        const int k0 = (pair ? chunk - kc : chunk) * 32;
        const float* A = pair ? A1 : A0;
        const float* B = pair ? B1t : B0t;
        const uint32_t da = sbase + (uint32_t)buf * (TILE_F * 4);
        const uint32_t db = sbase + (uint32_t)(2 + buf) * (TILE_F * 4);
#pragma unroll
        for (int l = 0; l < 4; ++l) {
            int row = srow + l * 32;
            cp_async16(da + (uint32_t)(row * PADK + sc4 * 4) * 4,
                       A + (size_t)(m0 + row) * K + k0 + sc4 * 4);
        }
#pragma unroll
        for (int l = 0; l < 4; ++l) {
            int row = srow + l * 32;
            cp_async16(db + (uint32_t)(row * PADK + sc4 * 4) * 4,
                       B + (size_t)(n0 + row) * K + k0 + sc4 * 4);
        }
    };

    stage(0, 0);
    CP_COMMIT();
    int buf = 0;
    for (int chunk = 0; chunk < T; ++chunk) {
        if (chunk + 1 < T) {
            stage(chunk + 1, buf ^ 1);
            CP_COMMIT();
            CP_WAIT(1);
        } else {
            CP_WAIT(0);
        }
        __syncthreads();

        const float* As = sm + buf * TILE_F;
        const float* Bs = sm + (2 + buf) * TILE_F;
        const int q2 = (lane & 3) * 2;
        const int rr = lane >> 2;
#pragma unroll
        for (int ks = 0; ks < 4; ++ks) {
            uint32_t a[4][4], b[4][2];
            const int cc = ks * 8 + q2;
#pragma unroll
            for (int mi = 0; mi < 4; ++mi) {
                const float* p = As + (wm * 64 + mi * 16 + rr) * PADK + cc;
                float2 lo = *(const float2*)p;              // k, k+4 (row r)
                float2 hi = *(const float2*)(p + 8 * PADK); // k, k+4 (row r+8)
                a[mi][0] = __float_as_uint(lo.x);
                a[mi][1] = __float_as_uint(hi.x);
                a[mi][2] = __float_as_uint(lo.y);
                a[mi][3] = __float_as_uint(hi.y);
            }
#pragma unroll
            for (int ni = 0; ni < 4; ++ni) {
                const float* p = Bs + (wn * 32 + ni * 8 + rr) * PADK + cc;
                float2 v = *(const float2*)p;
                b[ni][0] = __float_as_uint(v.x);
                b[ni][1] = __float_as_uint(v.y);
            }
#pragma unroll
            for (int mi = 0; mi < 4; ++mi)
#pragma unroll
                for (int ni = 0; ni < 4; ++ni)
                    mma_tf32(acc[mi][ni], a[mi][0], a[mi][1], a[mi][2], a[mi][3],
                             b[ni][0], b[ni][1]);
        }
        __syncthreads();
        buf ^= 1;
    }

    // epilogue
#pragma unroll
    for (int ni = 0; ni < 4; ++ni) {
        const int n = n0 + wn * 32 + ni * 8 + 2 * (lane & 3);
        const float bx = __ldg(bias + n), by = __ldg(bias + n + 1);
#pragma unroll
        for (int mi = 0; mi < 4; ++mi) {
            const int m = m0 + wm * 64 + mi * 16 + (lane >> 2);
            float v00 = acc[mi][ni][0] + bx, v01 = acc[mi][ni][1] + by;
            float v10 = acc[mi][ni][2] + bx, v11 = acc[mi][ni][3] + by;
            if (INTERMEDIATE) {
                v00 = cvt_tf32(fmaxf(v00, 0.f)); v01 = cvt_tf32(fmaxf(v01, 0.f));
                v10 = cvt_tf32(fmaxf(v10, 0.f)); v11 = cvt_tf32(fmaxf(v11, 0.f));
                const int g = n & ~7;
                const int p0 = g | perm8(n & 7), p1 = g | perm8((n + 1) & 7);
                C[(size_t)m * N + p0] = v00;
                C[(size_t)m * N + p1] = v01;
                C[(size_t)(m + 8) * N + p0] = v10;
                C[(size_t)(m + 8) * N + p1] = v11;
            } else {
                *(float2*)(C + (size_t)m * N + n) = make_float2(v00, v01);
                *(float2*)(C + (size_t)(m + 8) * N + n) = make_float2(v10, v11);
            }
        }
    }
}

// ---------------------------------------------------------------------------
extern "C" void kernel_launch(void* const* d_in, const int* in_sizes, int n_in,
                              void* d_out, int out_size) {
    const float* x   = (const float*)d_in[0];
    const float* Ws0 = (const float*)d_in[1];
    const float* Wn0 = (const float*)d_in[2];
    const float* b0  = (const float*)d_in[3];
    const float* Ws1 = (const float*)d_in[4];
    const float* Wn1 = (const float*)d_in[5];
    const float* b1  = (const float*)d_in[6];
    const float* Ws2 = (const float*)d_in[7];
    const float* Wn2 = (const float*)d_in[8];
    const float* b2  = (const float*)d_in[9];
    const int*   e0  = (const int*)d_in[10];
    const int*   e1  = (const int*)d_in[11];
    const int*   e2  = (const int*)d_in[12];
    float* out = (float*)d_out;

    float *xr, *neigh0, *h1, *neigh1, *h2, *neigh2;
    float *Wt0s, *Wt0n, *Wt1s, *Wt1n, *Wt2s, *Wt2n;
    cudaGetSymbolAddress((void**)&xr,     g_xr);
    cudaGetSymbolAddress((void**)&neigh0, g_neigh0);
    cudaGetSymbolAddress((void**)&h1,     g_h1);
    cudaGetSymbolAddress((void**)&neigh1, g_neigh1);
    cudaGetSymbolAddress((void**)&h2,     g_h2);
    cudaGetSymbolAddress((void**)&neigh2, g_neigh2);
    cudaGetSymbolAddress((void**)&Wt0s,   g_Wt0s);
    cudaGetSymbolAddress((void**)&Wt0n,   g_Wt0n);
    cudaGetSymbolAddress((void**)&Wt1s,   g_Wt1s);
    cudaGetSymbolAddress((void**)&Wt1n,   g_Wt1n);
    cudaGetSymbolAddress((void**)&Wt2s,   g_Wt2s);
    cudaGetSymbolAddress((void**)&Wt2n,   g_Wt2n);

    cudaFuncSetAttribute(sage_mma_gemm<true>,
                         cudaFuncAttributeMaxDynamicSharedMemorySize, SMEM_GEMM_BYTES);
    cudaFuncSetAttribute(sage_mma_gemm<false>,
                         cudaFuncAttributeMaxDynamicSharedMemorySize, SMEM_GEMM_BYTES);

    // Launch order chosen so the 6th launch is the big layer-0 GEMM (ncu -s 5 -c 1).
    // 1: gather0 (reads raw x, writes rounded+permuted neigh0)
    gather_mean_kernel<true><<<N1_SZ / 8, dim3(IN_DIM / 8, 8)>>>(x, e0, neigh0, IN_DIM / 8, N1_SZ);
    // 2: rounded+permuted copy of x[:N1]
    {
        size_t n8 = (size_t)N1_SZ * IN_DIM / 8;
        round_perm_kernel<<<(unsigned)((n8 + 255) / 256), 256>>>(x, xr, n8);
    }
    // 3-5: weight transposes for layers 0 and 1 (self)
    transpose_tf32_kernel<<<dim3(H_DIM / 32, IN_DIM / 32), dim3(32, 8)>>>(Ws0, Wt0s, IN_DIM, H_DIM);
    transpose_tf32_kernel<<<dim3(H_DIM / 32, IN_DIM / 32), dim3(32, 8)>>>(Wn0, Wt0n, IN_DIM, H_DIM);
    transpose_tf32_kernel<<<dim3(H_DIM / 32, H_DIM / 32), dim3(32, 8)>>>(Ws1, Wt1s, H_DIM, H_DIM);
    // 6: Layer-0 dual GEMM  x_r/neigh0 [123904,256] -> h1 [123904,512]
    sage_mma_gemm<true><<<dim3(H_DIM / 128, N1_SZ / 128), 256, SMEM_GEMM_BYTES>>>(
        xr, neigh0, Wt0s, Wt0n, b0, h1, IN_DIM, H_DIM);
    // 7: remaining layer-1 weight transpose
    transpose_tf32_kernel<<<dim3(H_DIM / 32, H_DIM / 32), dim3(32, 8)>>>(Wn1, Wt1n, H_DIM, H_DIM);
    // 8: gather1 (h1 already permuted+rounded; elementwise mean keeps layout)
    gather_mean_kernel<false><<<N2_SZ / 4, dim3(H_DIM / 8, 4)>>>(h1, e1, neigh1, H_DIM / 8, N2_SZ);
    // 9: Layer-1 dual GEMM -> h2 [11264,512]
    sage_mma_gemm<true><<<dim3(H_DIM / 128, N2_SZ / 128), 256, SMEM_GEMM_BYTES>>>(
        h1, neigh1, Wt1s, Wt1n, b1, h2, H_DIM, H_DIM);
    // 10-11: layer-2 weight transposes
    transpose_tf32_kernel<<<dim3(C_DIM / 32, H_DIM / 32), dim3(32, 8)>>>(Ws2, Wt2s, H_DIM, C_DIM);
    transpose_tf32_kernel<<<dim3(C_DIM / 32, H_DIM / 32), dim3(32, 8)>>>(Wn2, Wt2n, H_DIM, C_DIM);
    // 12: gather2
    gather_mean_kernel<false><<<SEEDS_SZ / 4, dim3(H_DIM / 8, 4)>>>(h2, e2, neigh2, H_DIM / 8, SEEDS_SZ);
    // 13: Layer-2 dual GEMM -> out [1024,256] (canonical layout, no ReLU)
    sage_mma_gemm<false><<<dim3(C_DIM / 128, SEEDS_SZ / 128), 256, SMEM_GEMM_BYTES>>>(
        h2, neigh2, Wt2s, Wt2n, b2, out, H_DIM, C_DIM);
}